// round 14
// baseline (speedup 1.0000x reference)
#include <cuda_runtime.h>
#include <cstddef>
#include <cstdint>

#define RR    64
#define NN    512
#define DIMM  128
#define HH    8
#define DHH   64
#define INNERR 512
#define DPAIRR 128
#define KBIG  4096
#define PIPE  3

// ---------------- scratch ------------------------------------------------------
__device__ float g_xr [(size_t)RR * NN * DIMM];
__device__ float g_wq [DIMM * INNERR];
__device__ float g_wkv[DIMM * 2 * INNERR];
__device__ float g_wo [INNERR * DIMM];
__device__ float g_wsk[DIMM * DIMM];
__device__ float g_wsq[DIMM * DIMM];
__device__ float g_q  [(size_t)RR * NN * INNERR];  // [r*512+n][h*64+d] = w*q*0.125 (tf32)
__device__ float g_k  [(size_t)RR * NN * INNERR];
__device__ float g_v  [(size_t)RR * NN * INNERR];
__device__ float g_sk [(size_t)RR * NN * DIMM];
__device__ float g_sq [(size_t)NN * DIMM];
__device__ float g_wT [(size_t)HH * RR * NN];      // [h][r][n] (x0.125)
__device__ float g_dots [(size_t)HH * NN * NN];    // split-K part 0 / attn
__device__ float g_dots1[(size_t)HH * NN * NN];
__device__ float g_dots2[(size_t)HH * NN * NN];
__device__ float g_dots3[(size_t)HH * NN * NN];
__device__ float g_pb [(size_t)HH * NN * NN];
__device__ float g_ctx[(size_t)RR * NN * INNERR];

// ---------------- helpers ------------------------------------------------------
__device__ __forceinline__ unsigned f2tf(float f)
{
    unsigned u;
    asm("cvt.rna.tf32.f32 %0, %1;" : "=r"(u) : "f"(f));
    return u;
}
__device__ __forceinline__ float f2tff(float f) { return __uint_as_float(f2tf(f)); }

__device__ __forceinline__ void mma8(float* d, const unsigned* a, const unsigned* b)
{
    asm volatile(
        "mma.sync.aligned.m16n8k8.row.col.f32.tf32.tf32.f32 "
        "{%0,%1,%2,%3},{%4,%5,%6,%7},{%8,%9},{%0,%1,%2,%3};"
        : "+f"(d[0]), "+f"(d[1]), "+f"(d[2]), "+f"(d[3])
        : "r"(a[0]), "r"(a[1]), "r"(a[2]), "r"(a[3]), "r"(b[0]), "r"(b[1]));
}

__device__ __forceinline__ void cp16(void* dst, const void* src)
{
    unsigned s = (unsigned)__cvta_generic_to_shared(dst);
    asm volatile("cp.async.cg.shared.global [%0], [%1], 16;\n" :: "r"(s), "l"(src));
}
__device__ __forceinline__ void cp_commit() { asm volatile("cp.async.commit_group;\n"); }
template<int W> __device__ __forceinline__ void cp_wait()
{
    asm volatile("cp.async.wait_group %0;\n" :: "n"(W));
}

// ---------------- launch 1: tf32 rounding --------------------------------------
__global__ void round_all(const float* __restrict__ x,
                          const float* __restrict__ Wq,
                          const float* __restrict__ Wkv,
                          const float* __restrict__ Wo,
                          const float* __restrict__ Wsk,
                          const float* __restrict__ Wsq)
{
    const int X4  = (RR * NN * DIMM) / 4;
    const int Q4  = (DIMM * INNERR) / 4;
    const int KV4 = (DIMM * 2 * INNERR) / 4;
    const int O4  = (INNERR * DIMM) / 4;
    const int S4  = (DIMM * DIMM) / 4;
    int i = blockIdx.x * blockDim.x + threadIdx.x;
    const float4* src; float4* dst; int j;
    if      (i < X4)                        { src = (const float4*)x;   dst = (float4*)g_xr;  j = i; }
    else if (i < X4 + Q4)                   { src = (const float4*)Wq;  dst = (float4*)g_wq;  j = i - X4; }
    else if (i < X4 + Q4 + KV4)             { src = (const float4*)Wkv; dst = (float4*)g_wkv; j = i - X4 - Q4; }
    else if (i < X4 + Q4 + KV4 + O4)        { src = (const float4*)Wo;  dst = (float4*)g_wo;  j = i - X4 - Q4 - KV4; }
    else if (i < X4 + Q4 + KV4 + O4 + S4)   { src = (const float4*)Wsk; dst = (float4*)g_wsk; j = i - X4 - Q4 - KV4 - O4; }
    else if (i < X4 + Q4 + KV4 + O4 + 2*S4) { src = (const float4*)Wsq; dst = (float4*)g_wsq; j = i - X4 - Q4 - KV4 - O4 - S4; }
    else return;
    float4 v = src[j];
    v.x = f2tff(v.x); v.y = f2tff(v.y); v.z = f2tff(v.z); v.w = f2tff(v.w);
    dst[j] = v;
}

// ---------------- launch 2: merged sk + sq projections -------------------------
#define AS(s, i, k) Asb[((s) * 128 + (i)) * 20 + (k)]
#define BS(s, i, k) Bsb[((s) * 16 + (i)) * 136 + (k)]
__global__ void __launch_bounds__(256)
skq_gemm(const float* __restrict__ bsk, const float* __restrict__ bsq)
{
    extern __shared__ float smem[];
    float* Asb = smem;
    float* Bsb = smem + PIPE * 128 * 20;
    const bool is_sk = blockIdx.y < 256;
    const int i0 = (is_sk ? blockIdx.y : (blockIdx.y - 256)) * 128;
    const float* B = is_sk ? g_wsk : g_wsq;
    const float* bias = is_sk ? bsk : bsq;
    float* C = is_sk ? g_sk : g_sq;

    const int t = threadIdx.x, lane = t & 31, warp = t >> 5;
    const int wm = (warp >> 2) * 64, wn = (warp & 3) * 32;
    const int g = lane >> 2, c = lane & 3;
    const int ar = t >> 2, ak = 4 * (t & 3);
    const int bk = t >> 5, bn = 4 * (t & 31);
    const float* Ab = g_xr + (size_t)i0 * DIMM;
    const int nit = DIMM / 16;   // 8

    auto stage = [&](int it) {
        if (it < nit) {
            const int k0 = it * 16, s = it % PIPE;
            cp16(&AS(s, ar, ak),      Ab + (size_t)ar * DIMM + k0 + ak);
            cp16(&AS(s, ar + 64, ak), Ab + (size_t)(ar + 64) * DIMM + k0 + ak);
            cp16(&BS(s, bk, bn),      B + (size_t)(k0 + bk) * DIMM + bn);
            cp16(&BS(s, bk + 8, bn),  B + (size_t)(k0 + bk + 8) * DIMM + bn);
        }
        cp_commit();
    };

    float acc[4][4][4] = {};
    stage(0); stage(1);
    for (int it = 0; it < nit; ++it) {
        const int s = it % PIPE;
        cp_wait<1>();
        __syncthreads();
#pragma unroll
        for (int ks = 0; ks < 16; ks += 8) {
            unsigned af[4][4], bf[4][2];
#pragma unroll
            for (int mf = 0; mf < 4; mf++) {
                int r0 = wm + mf * 16;
                af[mf][0] = __float_as_uint(AS(s, r0 + g, ks + c));
                af[mf][1] = __float_as_uint(AS(s, r0 + g + 8, ks + c));
                af[mf][2] = __float_as_uint(AS(s, r0 + g, ks + c + 4));
                af[mf][3] = __float_as_uint(AS(s, r0 + g + 8, ks + c + 4));
            }
#pragma unroll
            for (int nf = 0; nf < 4; nf++) {
                int n = wn + nf * 8 + g;
                bf[nf][0] = __float_as_uint(BS(s, ks + c, n));
                bf[nf][1] = __float_as_uint(BS(s, ks + c + 4, n));
            }
#pragma unroll
            for (int mf = 0; mf < 4; mf++)
#pragma unroll
                for (int nf = 0; nf < 4; nf++) mma8(acc[mf][nf], af[mf], bf[nf]);
        }
        stage(it + 2);
    }

#pragma unroll
    for (int mf = 0; mf < 4; mf++) {
        const int row0 = i0 + wm + mf * 16 + g;
#pragma unroll
        for (int nf = 0; nf < 4; nf++) {
            const int col = wn + nf * 8 + 2 * c;
            float b0 = bias[col], b1 = bias[col + 1];
            *(float2*)(C + (size_t)row0 * DIMM + col) =
                make_float2(acc[mf][nf][0] + b0, acc[mf][nf][1] + b1);
            *(float2*)(C + (size_t)(row0 + 8) * DIMM + col) =
                make_float2(acc[mf][nf][2] + b0, acc[mf][nf][3] + b1);
        }
    }
}

// ---------------- launch 3: row weights (coalesced) -> g_wT[h][r][n] -----------
// 512 blocks (one per n), 256 threads. Coalesced sk row reads + shfl reduction.
__global__ void __launch_bounds__(256)
rowweight_kernel()
{
    const int n = blockIdx.x;
    const int t = threadIdx.x, lane = t & 31, warp = t >> 5;
    __shared__ float sqs[128];
    __shared__ float wlogs[64 * 8];   // [r][h]
    if (t < 128) sqs[t] = g_sq[(size_t)n * DIMM + t];
    __syncthreads();

    const int c = t & 127;            // channel
    const int half = t >> 7;          // 0/1: two rows per iteration
    for (int rr = half; rr < RR; rr += 2) {
        float val = g_sk[((size_t)rr * NN + n) * DIMM + c] * sqs[c];
        // reduce within 16-lane groups (one head per group)
        val += __shfl_xor_sync(0xffffffffu, val, 8);
        val += __shfl_xor_sync(0xffffffffu, val, 4);
        val += __shfl_xor_sync(0xffffffffu, val, 2);
        val += __shfl_xor_sync(0xffffffffu, val, 1);
        if ((lane & 15) == 0)
            wlogs[rr * 8 + (c >> 4)] = val * 0.25f;
    }
    __syncthreads();

    // per-head softmax over r: warp w handles head w
    if (warp < 8) {
        const int h = warp;
        float v0 = wlogs[lane * 8 + h];
        float v1 = wlogs[(lane + 32) * 8 + h];
        float m = fmaxf(v0, v1);
#pragma unroll
        for (int o = 16; o; o >>= 1) m = fmaxf(m, __shfl_xor_sync(0xffffffffu, m, o));
        float e0 = expf(v0 - m), e1 = expf(v1 - m);
        float s = e0 + e1;
#pragma unroll
        for (int o = 16; o; o >>= 1) s += __shfl_xor_sync(0xffffffffu, s, o);
        const float inv = 0.125f / s;
        g_wT[((size_t)h * RR + lane) * NN + n]      = e0 * inv;
        g_wT[((size_t)h * RR + lane + 32) * NN + n] = e1 * inv;
    }
}

// ---------------- launch 4 (MEASURED): q + kv, CTA 128x64, warp 32x32 ----------
#define BSQ(s, i, k) Bsb[((s) * 16 + (i)) * 72 + (k)]
__global__ void __launch_bounds__(256)
qkv_gemm()
{
    extern __shared__ float smem[];
    float* Asb = smem;                     // [PIPE][128][20]
    float* Bsb = smem + PIPE * 128 * 20;   // [PIPE][16][72]
    const bool isq = blockIdx.x < 8;
    const float* Bmat = isq ? g_wq : g_wkv;
    const int ldb = isq ? 512 : 1024;
    const int j0 = (isq ? blockIdx.x : (blockIdx.x - 8)) * 64;
    const int i0 = blockIdx.y * 128;

    const int t = threadIdx.x, lane = t & 31, warp = t >> 5;
    const int wm = (warp >> 1) * 32, wn = (warp & 1) * 32;
    const int g = lane >> 2, c = lane & 3;
    const int ar = t >> 2, ak = 4 * (t & 3);
    const int bk = t >> 4, bn = 4 * (t & 15);

    const float* Ab = g_xr + (size_t)i0 * DIMM;
    const float* Bb = Bmat + j0;
    const int nit = DIMM / 16;   // 8

    auto stage = [&](int it) {
        if (it < nit) {
            const int k0 = it * 16, s = it % PIPE;
            cp16(&AS(s, ar, ak),      Ab + (size_t)ar * DIMM + k0 + ak);
            cp16(&AS(s, ar + 64, ak), Ab + (size_t)(ar + 64) * DIMM + k0 + ak);
            cp16(&BSQ(s, bk, bn),     Bb + (size_t)(k0 + bk) * ldb + bn);
        }
        cp_commit();
    };

    float acc[2][4][4] = {};
    stage(0); stage(1);
    for (int it = 0; it < nit; ++it) {
        const int s = it % PIPE;
        cp_wait<1>();
        __syncthreads();
#pragma unroll
        for (int ks = 0; ks < 16; ks += 8) {
            unsigned af[2][4], bf[4][2];
#pragma unroll
            for (int mf = 0; mf < 2; mf++) {
                int r0 = wm + mf * 16;
                af[mf][0] = __float_as_uint(AS(s, r0 + g, ks + c));
                af[mf][1] = __float_as_uint(AS(s, r0 + g + 8, ks + c));
                af[mf][2] = __float_as_uint(AS(s, r0 + g, ks + c + 4));
                af[mf][3] = __float_as_uint(AS(s, r0 + g + 8, ks + c + 4));
            }
#pragma unroll
            for (int nf = 0; nf < 4; nf++) {
                int n = wn + nf * 8 + g;
                bf[nf][0] = __float_as_uint(BSQ(s, ks + c, n));
                bf[nf][1] = __float_as_uint(BSQ(s, ks + c + 4, n));
            }
#pragma unroll
            for (int mf = 0; mf < 2; mf++)
#pragma unroll
                for (int nf = 0; nf < 4; nf++) mma8(acc[mf][nf], af[mf], bf[nf]);
        }
        stage(it + 2);
    }

#pragma unroll
    for (int mf = 0; mf < 2; mf++) {
        const int row0 = i0 + wm + mf * 16 + g;
        const int r = row0 >> 9;
#pragma unroll
        for (int nf = 0; nf < 4; nf++) {
            const int col = j0 + wn + nf * 8 + 2 * c;
            float v0 = acc[mf][nf][0], v1 = acc[mf][nf][1];
            float v2 = acc[mf][nf][2], v3 = acc[mf][nf][3];
            float* dst0; float* dst1;
            if (isq) {
                const int ch = col >> 6;
                float w0 = g_wT[((size_t)ch * RR + r) * NN + (row0 & 511)];
                float w1 = g_wT[((size_t)ch * RR + r) * NN + ((row0 + 8) & 511)];
                v0 *= w0; v1 *= w0; v2 *= w1; v3 *= w1;
                dst0 = g_q + (size_t)row0 * 512 + col;
                dst1 = g_q + (size_t)(row0 + 8) * 512 + col;
            } else if (col < 512) {
                dst0 = g_k + (size_t)row0 * 512 + col;
                dst1 = g_k + (size_t)(row0 + 8) * 512 + col;
            } else {
                dst0 = g_v + (size_t)row0 * 512 + col - 512;
                dst1 = g_v + (size_t)(row0 + 8) * 512 + col - 512;
            }
            *(float2*)dst0 = make_float2(f2tff(v0), f2tff(v1));
            *(float2*)dst1 = make_float2(f2tff(v2), f2tff(v3));
        }
    }
}

// ---------------- launch 5: MERGED dots (z<32) + pairbias (z>=32) --------------
__global__ void __launch_bounds__(128)
dots_pb(const float* __restrict__ pair,
        const float* __restrict__ lng,
        const float* __restrict__ lnb,
        const float* __restrict__ Wp)
{
    extern __shared__ float smem[];
    const int t = threadIdx.x, lane = t & 31, warp = t >> 5;

    if (blockIdx.z >= 32) {
        // ---------- pairbias: 32 pairs per CTA, 4 lanes per pair ----------
        float* gw   = smem;          // [8][160]
        float* cons = smem + 1280;   // 16
        for (int i = t; i < 1024; i += 128) {
            const int h = i >> 7, cc = i & 127;
            gw[h * 160 + (cc >> 5) * 40 + (cc & 31)] = lng[cc] * Wp[cc * 8 + h];
        }
        if (t < 16) {
            const int h = t & 7;
            const float* coef = (t < 8) ? lnb : lng;
            float s = 0.f;
            for (int cc = 0; cc < 128; cc++) s += coef[cc] * Wp[cc * 8 + h];
            cons[t] = s;
        }
        __syncthreads();

        const int cta = (blockIdx.z - 32) * 16 + blockIdx.y * 4 + blockIdx.x;
        const int q = lane & 3, p = lane >> 2;
        const size_t pidx = (size_t)cta * 32 + warp * 8 + p;
        const float* xp = pair + pidx * DPAIRR + q * 32;

        float x[32];
#pragma unroll
        for (int j = 0; j < 8; j++) {
            float4 v = *(const float4*)(xp + j * 4);
            x[j * 4] = v.x; x[j * 4 + 1] = v.y; x[j * 4 + 2] = v.z; x[j * 4 + 3] = v.w;
        }
        float s1 = 0.f, s2 = 0.f;
#pragma unroll
        for (int j = 0; j < 32; j++) { s1 += x[j]; s2 += x[j] * x[j]; }
        s1 += __shfl_xor_sync(0xffffffffu, s1, 1);
        s1 += __shfl_xor_sync(0xffffffffu, s1, 2);
        s2 += __shfl_xor_sync(0xffffffffu, s2, 1);
        s2 += __shfl_xor_sync(0xffffffffu, s2, 2);
        const float mu  = s1 * (1.f / 128.f);
        const float inv = rsqrtf(s2 * (1.f / 128.f) - mu * mu + 1e-5f);

        float S[8];
#pragma unroll
        for (int h = 0; h < 8; h++) {
            const float* wr = gw + h * 160 + q * 40;
            float a2 = 0.f;
#pragma unroll
            for (int j = 0; j < 8; j++) {
                float4 w4 = *(const float4*)(wr + j * 4);
                a2 += x[j*4] * w4.x + x[j*4+1] * w4.y + x[j*4+2] * w4.z + x[j*4+3] * w4.w;
            }
            S[h] = a2;
        }
#pragma unroll
        for (int h = 0; h < 8; h++) {
            S[h] += __shfl_xor_sync(0xffffffffu, S[h], 1);
            S[h] += __shfl_xor_sync(0xffffffffu, S[h], 2);
        }
#pragma unroll
        for (int hh = 0; hh < 2; hh++) {
            const int h = q + hh * 4;
            g_pb[(size_t)h * (NN * NN) + pidx] = inv * (S[h] - mu * cons[8 + h]) + cons[h];
        }
        return;
    }

    // ---------- dots: NT GEMM, 64x64 warp tiles, split-K 4 ----------
    const int h = blockIdx.z & 7, part = blockIdx.z >> 3;
    const int i0 = blockIdx.y * 128, j0 = blockIdx.x * 128;
    float* Asb = smem;
    float* Bsb = smem + PIPE * 128 * 20;
    const int wm = (warp >> 1) * 64, wn = (warp & 1) * 64;
    const int g = lane >> 2, c = lane & 3;
    const int lr = t >> 2;
    const int lq = (t & 3) * 4;
    const int nit = 1024 / 16;   // 64

    auto stage = [&](int it) {
        if (it < nit) {
            const int kg = part * 1024 + it * 16;
            const int r = kg >> 6, d0 = (kg & 63) + lq;
            const float* Abase = g_q + ((size_t)r * NN + i0) * 512 + h * 64 + d0;
            const float* Bbase = g_k + ((size_t)r * NN + j0) * 512 + h * 64 + d0;
            const int s = it % PIPE;
#pragma unroll
            for (int rr = 0; rr < 128; rr += 32) {
                cp16(&Asb[((size_t)s * 128 + lr + rr) * 20 + lq],
                     Abase + (size_t)(lr + rr) * 512);
                cp16(&Bsb[((size_t)s * 128 + lr + rr) * 20 + lq],
                     Bbase + (size_t)(lr + rr) * 512);
            }
        }
        cp_commit();
    };

    float acc[4][8][4] = {};
    stage(0); stage(1);
    for (int it = 0; it < nit; ++it) {
        const int s = it % PIPE;
        cp_wait<1>();
        __syncthreads();
#pragma unroll
        for (int ks = 0; ks < 16; ks += 8) {
            unsigned af[4][4], bf[8][2];
#pragma unroll
            for (int mf = 0; mf < 4; mf++) {
                int r0 = wm + mf * 16;
                af[mf][0] = __float_as_uint(Asb[((size_t)s * 128 + r0 + g) * 20 + ks + c]);
                af[mf][1] = __float_as_uint(Asb[((size_t)s * 128 + r0 + g + 8) * 20 + ks + c]);
                af[mf][2] = __float_as_uint(Asb[((size_t)s * 128 + r0 + g) * 20 + ks + c + 4]);
                af[mf][3] = __float_as_uint(Asb[((size_t)s * 128 + r0 + g + 8) * 20 + ks + c + 4]);
            }
#pragma unroll
            for (int nf = 0; nf < 8; nf++) {
                int n = wn + nf * 8 + g;
                bf[nf][0] = __float_as_uint(Bsb[((size_t)s * 128 + n) * 20 + ks + c]);
                bf[nf][1] = __float_as_uint(Bsb[((size_t)s * 128 + n) * 20 + ks + c + 4]);
            }
#pragma unroll
            for (int mf = 0; mf < 4; mf++)
#pragma unroll
                for (int nf = 0; nf < 8; nf++) mma8(acc[mf][nf], af[mf], bf[nf]);
        }
        stage(it + 2);
    }

    float* Cb = (part == 0 ? g_dots : part == 1 ? g_dots1 : part == 2 ? g_dots2 : g_dots3)
                + (size_t)h * (NN * NN);
#pragma unroll
    for (int mf = 0; mf < 4; mf++) {
        const int row = i0 + wm + mf * 16 + g;
#pragma unroll
        for (int nf = 0; nf < 8; nf++) {
            const int col = j0 + wn + nf * 8 + 2 * c;
            *(float2*)(Cb + (size_t)row * NN + col) =
                make_float2(acc[mf][nf][0], acc[mf][nf][1]);
            *(float2*)(Cb + (size_t)(row + 8) * NN + col) =
                make_float2(acc[mf][nf][2], acc[mf][nf][3]);
        }
    }
}

// ---------------- launch 6: softmax (sum 4 parts + pb, softmax, tf32) ----------
__global__ void softmax_kernel()
{
    const int i = blockIdx.x, h = blockIdx.y;
    const size_t off = ((size_t)h * NN + i) * NN;
    float* row = g_dots + off;
    const float* r1 = g_dots1 + off;
    const float* r2 = g_dots2 + off;
    const float* r3 = g_dots3 + off;
    const float* pbr = g_pb + off;
    const int t = threadIdx.x;  // 128
    __shared__ float red[128];
    float v[4];
    float mx = -1e30f;
#pragma unroll
    for (int e = 0; e < 4; e++) {
        const int j = t * 4 + e;
        v[e] = row[j] + r1[j] + r2[j] + r3[j] + pbr[j];
        mx = fmaxf(mx, v[e]);
    }
    red[t] = mx; __syncthreads();
#pragma unroll
    for (int s = 64; s; s >>= 1) { if (t < s) red[t] = fmaxf(red[t], red[t + s]); __syncthreads(); }
    const float M = red[0];
    __syncthreads();
    float sum = 0.f;
#pragma unroll
    for (int e = 0; e < 4; e++) { v[e] = expf(v[e] - M); sum += v[e]; }
    red[t] = sum; __syncthreads();
#pragma unroll
    for (int s = 64; s; s >>= 1) { if (t < s) red[t] += red[t + s]; __syncthreads(); }
    const float inv = 1.f / red[0];
#pragma unroll
    for (int e = 0; e < 4; e++) row[t * 4 + e] = f2tff(v[e] * inv);
}

// ---------------- launch 7: ctx NN GEMM, 64x64 warp tiles, 128 thr -------------
__global__ void __launch_bounds__(128)
ctx_nn()
{
    const int h  = blockIdx.z;
    const int i0 = blockIdx.y * 128, n0 = blockIdx.x * 128;
    extern __shared__ float smem[];
    float* Asb = smem;
    float* Bsb = smem + PIPE * 128 * 20;
    const int t = threadIdx.x, lane = t & 31, warp = t >> 5;
    const int wm = (warp >> 1) * 64, wn = (warp & 1) * 64;
    const int g = lane >> 2, c = lane & 3;
    const int lr = t >> 2, lq = (t & 3) * 4;
    const int bcol = (t & 31) * 4;
    const int brow = t >> 5;

    const float* Ab = g_dots + (size_t)h * (NN * NN) + (size_t)i0 * NN;
    const int cgB = n0 + bcol;
    const float* Bptr = g_v + ((size_t)(cgB >> 6) * NN) * 512 + h * 64 + (cgB & 63);
    const int nit = NN / 16;   // 32

    auto stage = [&](int it) {
        if (it < nit) {
            const int k0 = it * 16, s = it % PIPE;
#pragma unroll
            for (int rr = 0; rr < 128; rr += 32)
                cp16(&Asb[((size_t)s * 128 + lr + rr) * 20 + lq],
                     Ab + (size_t)(lr + rr) * NN + k0 + lq);
#pragma unroll
            for (int j = 0; j < 4; j++) {
                const int kr = brow + j * 4;
                cp16(&Bsb[((size_t)s * 16 + kr) * 136 + bcol],
                     Bptr + (size_t)(k0 + kr) * 512);
            }
        }
        cp_commit();
    };

    float acc[4][8][4] = {};
    stage(0); stage(1);
    for (int it = 0; it < nit; ++it) {
        const int s = it % PIPE;
        cp_wait<1>();
        __syncthreads();
#pragma unroll
        for (int ks = 0; ks < 16; ks += 8) {
            unsigned af[4][4], bf[8][2];
#pragma unroll
            for (int mf = 0; mf < 4; mf++) {
                int r0 = wm + mf * 16;
                af[mf][0] = __float_as_uint(Asb[((size_t)s * 128 + r0 + g) * 20 + ks + c]);
                af[mf][1] = __float_as_uint(Asb[((size_t)s * 128 + r0 + g + 8) * 20 + ks + c]);
                af[mf][2] = __float_as_uint(Asb[((size_t)s * 128 + r0 + g) * 20 + ks + c + 4]);
                af[mf][3] = __float_as_uint(Asb[((size_t)s * 128 + r0 + g + 8) * 20 + ks + c + 4]);
            }
#pragma unroll
            for (int nf = 0; nf < 8; nf++) {
                int n = wn + nf * 8 + g;
                bf[nf][0] = __float_as_uint(Bsb[((size_t)s * 16 + ks + c) * 136 + n]);
                bf[nf][1] = __float_as_uint(Bsb[((size_t)s * 16 + ks + c + 4) * 136 + n]);
            }
#pragma unroll
            for (int mf = 0; mf < 4; mf++)
#pragma unroll
                for (int nf = 0; nf < 8; nf++) mma8(acc[mf][nf], af[mf], bf[nf]);
        }
        stage(it + 2);
    }

#pragma unroll
    for (int mf = 0; mf < 4; mf++) {
        const int row = i0 + wm + mf * 16 + g;
#pragma unroll
        for (int nf = 0; nf < 8; nf++) {
            const int col = n0 + wn + nf * 8 + 2 * c;
            const int rg = col >> 6, dd = col & 63;
            float* p0 = g_ctx + ((size_t)rg * NN + row) * INNERR + h * 64 + dd;
            float* p1 = g_ctx + ((size_t)rg * NN + row + 8) * INNERR + h * 64 + dd;
            *(float2*)p0 = make_float2(acc[mf][nf][0], acc[mf][nf][1]);
            *(float2*)p1 = make_float2(acc[mf][nf][2], acc[mf][nf][3]);
        }
    }
}

// ---------------- launch 8: output projection, 64x64 warp tiles, 128 thr -------
__global__ void __launch_bounds__(128)
out_gemm(const float* __restrict__ bias, float* __restrict__ C)
{
    extern __shared__ float smem[];
    float* Asb = smem;
    float* Bsb = smem + PIPE * 128 * 20;
    const int t = threadIdx.x, lane = t & 31, warp = t >> 5;
    const int i0 = blockIdx.y * 128;
    const int wm = (warp >> 1) * 64, wn = (warp & 1) * 64;
    const int g = lane >> 2, c = lane & 3;
    const int lr = t >> 2, lq = (t & 3) * 4;
    const int bcol = (t & 31) * 4;
    const int brow = t >> 5;

    const float* Ab = g_ctx + (size_t)i0 * INNERR;
    const int nit = INNERR / 16;   // 32

    auto stage = [&](int it) {
        if (it < nit) {
            const int k0 = it * 16, s = it % PIPE;
#pragma unroll
            for (int rr = 0; rr < 128; rr += 32)
                cp16(&Asb[((size_t)s * 128 + lr + rr) * 20 + lq],
                     Ab + (size_t)(lr + rr) * INNERR + k0 + lq);
#pragma unroll
            for (int j = 0; j < 4; j++) {
                const int kr = brow + j * 4;
                cp16(&Bsb[((size_t)s * 16 + kr) * 136 + bcol],
                     g_wo + (size_t)(k0 + kr) * DIMM + bcol);
            }
        }
        cp_commit();
    };

    float acc[4][8][4] = {};
    stage(0); stage(1);
    for (int it = 0; it < nit; ++it) {
        const int s = it % PIPE;
        cp_wait<1>();
        __syncthreads();
#pragma unroll
        for (int ks = 0; ks < 16; ks += 8) {
            unsigned af[4][4], bf[8][2];
#pragma unroll
            for (int mf = 0; mf < 4; mf++) {
                int r0 = wm + mf * 16;
                af[mf][0] = __float_as_uint(Asb[((size_t)s * 128 + r0 + g) * 20 + ks + c]);
                af[mf][1] = __float_as_uint(Asb[((size_t)s * 128 + r0 + g + 8) * 20 + ks + c]);
                af[mf][2] = __float_as_uint(Asb[((size_t)s * 128 + r0 + g) * 20 + ks + c + 4]);
                af[mf][3] = __float_as_uint(Asb[((size_t)s * 128 + r0 + g + 8) * 20 + ks + c + 4]);
            }
#pragma unroll
            for (int nf = 0; nf < 8; nf++) {
                int n = wn + nf * 8 + g;
                bf[nf][0] = __float_as_uint(Bsb[((size_t)s * 16 + ks + c) * 136 + n]);
                bf[nf][1] = __float_as_uint(Bsb[((size_t)s * 16 + ks + c + 4) * 136 + n]);
            }
#pragma unroll
            for (int mf = 0; mf < 4; mf++)
#pragma unroll
                for (int nf = 0; nf < 8; nf++) mma8(acc[mf][nf], af[mf], bf[nf]);
        }
        stage(it + 2);
    }

#pragma unroll
    for (int mf = 0; mf < 4; mf++) {
        const int row0 = i0 + wm + mf * 16 + g;
#pragma unroll
        for (int nf = 0; nf < 8; nf++) {
            const int col = wn + nf * 8 + 2 * c;
            float b0 = bias[col], b1 = bias[col + 1];
            *(float2*)(C + (size_t)row0 * DIMM + col) =
                make_float2(acc[mf][nf][0] + b0, acc[mf][nf][1] + b1);
            *(float2*)(C + (size_t)(row0 + 8) * DIMM + col) =
                make_float2(acc[mf][nf][2] + b0, acc[mf][nf][3] + b1);
        }
    }
}

// ------------------------------ host ------------------------------------------
extern "C" void kernel_launch(void* const* d_in, const int* in_sizes, int n_in,
                              void* d_out, int out_size)
{
    const float* x     = (const float*)d_in[0];
    const float* pair  = (const float*)d_in[1];
    const float* Wq    = (const float*)d_in[2];
    const float* Wkv   = (const float*)d_in[3];
    const float* Wo    = (const float*)d_in[4];
    const float* bo    = (const float*)d_in[5];
    const float* lng   = (const float*)d_in[6];
    const float* lnb   = (const float*)d_in[7];
    const float* Wpair = (const float*)d_in[8];
    const float* Wsq   = (const float*)d_in[9];
    const float* bsq   = (const float*)d_in[10];
    const float* Wsk   = (const float*)d_in[11];
    const float* bsk   = (const float*)d_in[12];
    float* out = (float*)d_out;

    const int SM_GEMM = PIPE * (128 * 20 + 16 * 136) * 4;  // 56832
    const int SM_QKV  = PIPE * (128 * 20 + 16 * 72) * 4;   // 44544
    const int SM_DOTS = PIPE * (128 * 20) * 2 * 4;         // 61440
    cudaFuncSetAttribute(skq_gemm, cudaFuncAttributeMaxDynamicSharedMemorySize, SM_GEMM);
    cudaFuncSetAttribute(qkv_gemm, cudaFuncAttributeMaxDynamicSharedMemorySize, SM_QKV);
    cudaFuncSetAttribute(dots_pb,  cudaFuncAttributeMaxDynamicSharedMemorySize, SM_DOTS);
    cudaFuncSetAttribute(ctx_nn,   cudaFuncAttributeMaxDynamicSharedMemorySize, SM_GEMM);
    cudaFuncSetAttribute(out_gemm, cudaFuncAttributeMaxDynamicSharedMemorySize, SM_GEMM);

    const int TOT4 = (RR * NN * DIMM + DIMM * INNERR + DIMM * 2 * INNERR
                      + INNERR * DIMM + 2 * DIMM * DIMM) / 4;

    // 1: tf32 rounding
    round_all<<<(TOT4 + 255) / 256, 256>>>(x, Wq, Wkv, Wo, Wsk, Wsq);
    // 2: merged sk + sq projections
    skq_gemm<<<dim3(1, 260), 256, SM_GEMM>>>(bsk, bsq);
    // 3: row weights (coalesced)
    rowweight_kernel<<<NN, 256>>>();
    // 4: q + kv projections, CTA 128x64  (MEASURED SLOT)
    qkv_gemm<<<dim3(24, (RR * NN) / 128), 256, SM_QKV>>>();
    // 5: merged dots (split-K 4) + pair bias
    dots_pb<<<dim3(4, 4, 32 + 512), 128, SM_DOTS>>>(pair, lng, lnb, Wpair);
    // 6: softmax (sum 4 parts + pair bias)
    softmax_kernel<<<dim3(NN, HH), 128>>>();
    // 7: attn @ V
    ctx_nn<<<dim3(32, 4, HH), 128, SM_GEMM>>>();
    // 8: output projection
    out_gemm<<<dim3(1, (RR * NN) / 128), 128, SM_GEMM>>>(bo, out);
}

// round 17
// speedup vs baseline: 1.0226x; 1.0226x over previous
#include <cuda_runtime.h>
#include <cstddef>
#include <cstdint>

#define RR    64
#define NN    512
#define DIMM  128
#define HH    8
#define DHH   64
#define INNERR 512
#define DPAIRR 128
#define KBIG  4096
#define PIPE  3

// ---------------- scratch ------------------------------------------------------
__device__ float g_xr [(size_t)RR * NN * DIMM];
__device__ float g_wq [DIMM * INNERR];
__device__ float g_wkv[DIMM * 2 * INNERR];
__device__ float g_wo [INNERR * DIMM];
__device__ float g_wsk[DIMM * DIMM];
__device__ float g_wsq[DIMM * DIMM];
__device__ float g_q  [(size_t)RR * NN * INNERR];  // [r*512+n][h*64+d] = w*q*0.125 (tf32)
__device__ float g_k  [(size_t)RR * NN * INNERR];
__device__ float g_v  [(size_t)RR * NN * INNERR];
__device__ float g_sk [(size_t)RR * NN * DIMM];
__device__ float g_sq [(size_t)NN * DIMM];
__device__ float g_wT [(size_t)HH * RR * NN];      // [h][r][n] (x0.125)
__device__ float g_dots [(size_t)HH * NN * NN];    // split-K part 0 / attn
__device__ float g_dots1[(size_t)HH * NN * NN];
__device__ float g_dots2[(size_t)HH * NN * NN];
__device__ float g_dots3[(size_t)HH * NN * NN];
__device__ float g_pb [(size_t)HH * NN * NN];
__device__ float g_ctx[(size_t)RR * NN * INNERR];

// ---------------- helpers ------------------------------------------------------
__device__ __forceinline__ unsigned f2tf(float f)
{
    unsigned u;
    asm("cvt.rna.tf32.f32 %0, %1;" : "=r"(u) : "f"(f));
    return u;
}
__device__ __forceinline__ float f2tff(float f) { return __uint_as_float(f2tf(f)); }

__device__ __forceinline__ void mma8(float* d, const unsigned* a, const unsigned* b)
{
    asm volatile(
        "mma.sync.aligned.m16n8k8.row.col.f32.tf32.tf32.f32 "
        "{%0,%1,%2,%3},{%4,%5,%6,%7},{%8,%9},{%0,%1,%2,%3};"
        : "+f"(d[0]), "+f"(d[1]), "+f"(d[2]), "+f"(d[3])
        : "r"(a[0]), "r"(a[1]), "r"(a[2]), "r"(a[3]), "r"(b[0]), "r"(b[1]));
}

__device__ __forceinline__ void cp16(void* dst, const void* src)
{
    unsigned s = (unsigned)__cvta_generic_to_shared(dst);
    asm volatile("cp.async.cg.shared.global [%0], [%1], 16;\n" :: "r"(s), "l"(src));
}
__device__ __forceinline__ void cp_commit() { asm volatile("cp.async.commit_group;\n"); }
template<int W> __device__ __forceinline__ void cp_wait()
{
    asm volatile("cp.async.wait_group %0;\n" :: "n"(W));
}

// ---------------- launch 1: tf32 rounding --------------------------------------
__global__ void round_all(const float* __restrict__ x,
                          const float* __restrict__ Wq,
                          const float* __restrict__ Wkv,
                          const float* __restrict__ Wo,
                          const float* __restrict__ Wsk,
                          const float* __restrict__ Wsq)
{
    const int X4  = (RR * NN * DIMM) / 4;
    const int Q4  = (DIMM * INNERR) / 4;
    const int KV4 = (DIMM * 2 * INNERR) / 4;
    const int O4  = (INNERR * DIMM) / 4;
    const int S4  = (DIMM * DIMM) / 4;
    int i = blockIdx.x * blockDim.x + threadIdx.x;
    const float4* src; float4* dst; int j;
    if      (i < X4)                        { src = (const float4*)x;   dst = (float4*)g_xr;  j = i; }
    else if (i < X4 + Q4)                   { src = (const float4*)Wq;  dst = (float4*)g_wq;  j = i - X4; }
    else if (i < X4 + Q4 + KV4)             { src = (const float4*)Wkv; dst = (float4*)g_wkv; j = i - X4 - Q4; }
    else if (i < X4 + Q4 + KV4 + O4)        { src = (const float4*)Wo;  dst = (float4*)g_wo;  j = i - X4 - Q4 - KV4; }
    else if (i < X4 + Q4 + KV4 + O4 + S4)   { src = (const float4*)Wsk; dst = (float4*)g_wsk; j = i - X4 - Q4 - KV4 - O4; }
    else if (i < X4 + Q4 + KV4 + O4 + 2*S4) { src = (const float4*)Wsq; dst = (float4*)g_wsq; j = i - X4 - Q4 - KV4 - O4 - S4; }
    else return;
    float4 v = src[j];
    v.x = f2tff(v.x); v.y = f2tff(v.y); v.z = f2tff(v.z); v.w = f2tff(v.w);
    dst[j] = v;
}

// ---------------- launch 2: merged sk + sq projections -------------------------
#define AS(s, i, k) Asb[((s) * 128 + (i)) * 20 + (k)]
#define BS(s, i, k) Bsb[((s) * 16 + (i)) * 136 + (k)]
__global__ void __launch_bounds__(256)
skq_gemm(const float* __restrict__ bsk, const float* __restrict__ bsq)
{
    extern __shared__ float smem[];
    float* Asb = smem;
    float* Bsb = smem + PIPE * 128 * 20;
    const bool is_sk = blockIdx.y < 256;
    const int i0 = (is_sk ? blockIdx.y : (blockIdx.y - 256)) * 128;
    const float* B = is_sk ? g_wsk : g_wsq;
    const float* bias = is_sk ? bsk : bsq;
    float* C = is_sk ? g_sk : g_sq;

    const int t = threadIdx.x, lane = t & 31, warp = t >> 5;
    const int wm = (warp >> 2) * 64, wn = (warp & 3) * 32;
    const int g = lane >> 2, c = lane & 3;
    const int ar = t >> 2, ak = 4 * (t & 3);
    const int bk = t >> 5, bn = 4 * (t & 31);
    const float* Ab = g_xr + (size_t)i0 * DIMM;
    const int nit = DIMM / 16;   // 8

    auto stage = [&](int it) {
        if (it < nit) {
            const int k0 = it * 16, s = it % PIPE;
            cp16(&AS(s, ar, ak),      Ab + (size_t)ar * DIMM + k0 + ak);
            cp16(&AS(s, ar + 64, ak), Ab + (size_t)(ar + 64) * DIMM + k0 + ak);
            cp16(&BS(s, bk, bn),      B + (size_t)(k0 + bk) * DIMM + bn);
            cp16(&BS(s, bk + 8, bn),  B + (size_t)(k0 + bk + 8) * DIMM + bn);
        }
        cp_commit();
    };

    float acc[4][4][4] = {};
    stage(0); stage(1);
    for (int it = 0; it < nit; ++it) {
        const int s = it % PIPE;
        cp_wait<1>();
        __syncthreads();
#pragma unroll
        for (int ks = 0; ks < 16; ks += 8) {
            unsigned af[4][4], bf[4][2];
#pragma unroll
            for (int mf = 0; mf < 4; mf++) {
                int r0 = wm + mf * 16;
                af[mf][0] = __float_as_uint(AS(s, r0 + g, ks + c));
                af[mf][1] = __float_as_uint(AS(s, r0 + g + 8, ks + c));
                af[mf][2] = __float_as_uint(AS(s, r0 + g, ks + c + 4));
                af[mf][3] = __float_as_uint(AS(s, r0 + g + 8, ks + c + 4));
            }
#pragma unroll
            for (int nf = 0; nf < 4; nf++) {
                int n = wn + nf * 8 + g;
                bf[nf][0] = __float_as_uint(BS(s, ks + c, n));
                bf[nf][1] = __float_as_uint(BS(s, ks + c + 4, n));
            }
#pragma unroll
            for (int mf = 0; mf < 4; mf++)
#pragma unroll
                for (int nf = 0; nf < 4; nf++) mma8(acc[mf][nf], af[mf], bf[nf]);
        }
        stage(it + 2);
    }

#pragma unroll
    for (int mf = 0; mf < 4; mf++) {
        const int row0 = i0 + wm + mf * 16 + g;
#pragma unroll
        for (int nf = 0; nf < 4; nf++) {
            const int col = wn + nf * 8 + 2 * c;
            float b0 = bias[col], b1 = bias[col + 1];
            *(float2*)(C + (size_t)row0 * DIMM + col) =
                make_float2(acc[mf][nf][0] + b0, acc[mf][nf][1] + b1);
            *(float2*)(C + (size_t)(row0 + 8) * DIMM + col) =
                make_float2(acc[mf][nf][2] + b0, acc[mf][nf][3] + b1);
        }
    }
}

// ---------------- launch 3: row weights (coalesced) -> g_wT[h][r][n] -----------
__global__ void __launch_bounds__(256)
rowweight_kernel()
{
    const int n = blockIdx.x;
    const int t = threadIdx.x, lane = t & 31, warp = t >> 5;
    __shared__ float sqs[128];
    __shared__ float wlogs[64 * 8];   // [r][h]
    if (t < 128) sqs[t] = g_sq[(size_t)n * DIMM + t];
    __syncthreads();

    const int c = t & 127;
    const int half = t >> 7;
    for (int rr = half; rr < RR; rr += 2) {
        float val = g_sk[((size_t)rr * NN + n) * DIMM + c] * sqs[c];
        val += __shfl_xor_sync(0xffffffffu, val, 8);
        val += __shfl_xor_sync(0xffffffffu, val, 4);
        val += __shfl_xor_sync(0xffffffffu, val, 2);
        val += __shfl_xor_sync(0xffffffffu, val, 1);
        if ((lane & 15) == 0)
            wlogs[rr * 8 + (c >> 4)] = val * 0.25f;
    }
    __syncthreads();

    if (warp < 8) {
        const int h = warp;
        float v0 = wlogs[lane * 8 + h];
        float v1 = wlogs[(lane + 32) * 8 + h];
        float m = fmaxf(v0, v1);
#pragma unroll
        for (int o = 16; o; o >>= 1) m = fmaxf(m, __shfl_xor_sync(0xffffffffu, m, o));
        float e0 = expf(v0 - m), e1 = expf(v1 - m);
        float s = e0 + e1;
#pragma unroll
        for (int o = 16; o; o >>= 1) s += __shfl_xor_sync(0xffffffffu, s, o);
        const float inv = 0.125f / s;
        g_wT[((size_t)h * RR + lane) * NN + n]      = e0 * inv;
        g_wT[((size_t)h * RR + lane + 32) * NN + n] = e1 * inv;
    }
}

// ---------------- launch 4 (MEASURED): q + kv projections (R13 config) ---------
__global__ void __launch_bounds__(256)
qkv_gemm()
{
    extern __shared__ float smem[];
    float* Asb = smem;
    float* Bsb = smem + PIPE * 128 * 20;
    const bool isq = blockIdx.x < 4;
    const float* Bmat = isq ? g_wq : g_wkv;
    const int ldb = isq ? 512 : 1024;
    const int j0 = (isq ? blockIdx.x : (blockIdx.x - 4)) * 128;
    const int i0 = blockIdx.y * 128;

    const int t = threadIdx.x, lane = t & 31, warp = t >> 5;
    const int wm = (warp >> 2) * 64, wn = (warp & 3) * 32;
    const int g = lane >> 2, c = lane & 3;
    const int ar = t >> 2, ak = 4 * (t & 3);
    const int bk = t >> 5, bn = 4 * (t & 31);

    const float* Ab = g_xr + (size_t)i0 * DIMM;
    const float* Bb = Bmat + j0;
    const int nit = DIMM / 16;   // 8

    auto stage = [&](int it) {
        if (it < nit) {
            const int k0 = it * 16, s = it % PIPE;
            cp16(&AS(s, ar, ak),      Ab + (size_t)ar * DIMM + k0 + ak);
            cp16(&AS(s, ar + 64, ak), Ab + (size_t)(ar + 64) * DIMM + k0 + ak);
            cp16(&BS(s, bk, bn),      Bb + (size_t)(k0 + bk) * ldb + bn);
            cp16(&BS(s, bk + 8, bn),  Bb + (size_t)(k0 + bk + 8) * ldb + bn);
        }
        cp_commit();
    };

    float acc[4][4][4] = {};
    stage(0); stage(1);
    for (int it = 0; it < nit; ++it) {
        const int s = it % PIPE;
        cp_wait<1>();
        __syncthreads();
#pragma unroll
        for (int ks = 0; ks < 16; ks += 8) {
            unsigned af[4][4], bf[4][2];
#pragma unroll
            for (int mf = 0; mf < 4; mf++) {
                int r0 = wm + mf * 16;
                af[mf][0] = __float_as_uint(AS(s, r0 + g, ks + c));
                af[mf][1] = __float_as_uint(AS(s, r0 + g + 8, ks + c));
                af[mf][2] = __float_as_uint(AS(s, r0 + g, ks + c + 4));
                af[mf][3] = __float_as_uint(AS(s, r0 + g + 8, ks + c + 4));
            }
#pragma unroll
            for (int nf = 0; nf < 4; nf++) {
                int n = wn + nf * 8 + g;
                bf[nf][0] = __float_as_uint(BS(s, ks + c, n));
                bf[nf][1] = __float_as_uint(BS(s, ks + c + 4, n));
            }
#pragma unroll
            for (int mf = 0; mf < 4; mf++)
#pragma unroll
                for (int nf = 0; nf < 4; nf++) mma8(acc[mf][nf], af[mf], bf[nf]);
        }
        stage(it + 2);
    }

#pragma unroll
    for (int mf = 0; mf < 4; mf++) {
        const int row0 = i0 + wm + mf * 16 + g;
        const int r = row0 >> 9;
#pragma unroll
        for (int nf = 0; nf < 4; nf++) {
            const int col = j0 + wn + nf * 8 + 2 * c;
            float v0 = acc[mf][nf][0], v1 = acc[mf][nf][1];
            float v2 = acc[mf][nf][2], v3 = acc[mf][nf][3];
            float* dst0; float* dst1;
            if (isq) {
                const int ch = col >> 6;
                float w0 = g_wT[((size_t)ch * RR + r) * NN + (row0 & 511)];
                float w1 = g_wT[((size_t)ch * RR + r) * NN + ((row0 + 8) & 511)];
                v0 *= w0; v1 *= w0; v2 *= w1; v3 *= w1;
                dst0 = g_q + (size_t)row0 * 512 + col;
                dst1 = g_q + (size_t)(row0 + 8) * 512 + col;
            } else if (col < 512) {
                dst0 = g_k + (size_t)row0 * 512 + col;
                dst1 = g_k + (size_t)(row0 + 8) * 512 + col;
            } else {
                dst0 = g_v + (size_t)row0 * 512 + col - 512;
                dst1 = g_v + (size_t)(row0 + 8) * 512 + col - 512;
            }
            *(float2*)dst0 = make_float2(f2tff(v0), f2tff(v1));
            *(float2*)dst1 = make_float2(f2tff(v2), f2tff(v3));
        }
    }
}

// ---------------- launch 5: MERGED dots (z<32) + pairbias (z>=32) --------------
__global__ void __launch_bounds__(128)
dots_pb(const float* __restrict__ pair,
        const float* __restrict__ lng,
        const float* __restrict__ lnb,
        const float* __restrict__ Wp)
{
    extern __shared__ float smem[];
    const int t = threadIdx.x, lane = t & 31, warp = t >> 5;

    if (blockIdx.z >= 32) {
        float* gw   = smem;          // [8][160]
        float* cons = smem + 1280;   // 16
        for (int i = t; i < 1024; i += 128) {
            const int h = i >> 7, cc = i & 127;
            gw[h * 160 + (cc >> 5) * 40 + (cc & 31)] = lng[cc] * Wp[cc * 8 + h];
        }
        if (t < 16) {
            const int h = t & 7;
            const float* coef = (t < 8) ? lnb : lng;
            float s = 0.f;
            for (int cc = 0; cc < 128; cc++) s += coef[cc] * Wp[cc * 8 + h];
            cons[t] = s;
        }
        __syncthreads();

        const int cta = (blockIdx.z - 32) * 16 + blockIdx.y * 4 + blockIdx.x;
        const int q = lane & 3, p = lane >> 2;
        const size_t pidx = (size_t)cta * 32 + warp * 8 + p;
        const float* xp = pair + pidx * DPAIRR + q * 32;

        float x[32];
#pragma unroll
        for (int j = 0; j < 8; j++) {
            float4 v = *(const float4*)(xp + j * 4);
            x[j * 4] = v.x; x[j * 4 + 1] = v.y; x[j * 4 + 2] = v.z; x[j * 4 + 3] = v.w;
        }
        float s1 = 0.f, s2 = 0.f;
#pragma unroll
        for (int j = 0; j < 32; j++) { s1 += x[j]; s2 += x[j] * x[j]; }
        s1 += __shfl_xor_sync(0xffffffffu, s1, 1);
        s1 += __shfl_xor_sync(0xffffffffu, s1, 2);
        s2 += __shfl_xor_sync(0xffffffffu, s2, 1);
        s2 += __shfl_xor_sync(0xffffffffu, s2, 2);
        const float mu  = s1 * (1.f / 128.f);
        const float inv = rsqrtf(s2 * (1.f / 128.f) - mu * mu + 1e-5f);

        float S[8];
#pragma unroll
        for (int h = 0; h < 8; h++) {
            const float* wr = gw + h * 160 + q * 40;
            float a2 = 0.f;
#pragma unroll
            for (int j = 0; j < 8; j++) {
                float4 w4 = *(const float4*)(wr + j * 4);
                a2 += x[j*4] * w4.x + x[j*4+1] * w4.y + x[j*4+2] * w4.z + x[j*4+3] * w4.w;
            }
            S[h] = a2;
        }
#pragma unroll
        for (int h = 0; h < 8; h++) {
            S[h] += __shfl_xor_sync(0xffffffffu, S[h], 1);
            S[h] += __shfl_xor_sync(0xffffffffu, S[h], 2);
        }
#pragma unroll
        for (int hh = 0; hh < 2; hh++) {
            const int h = q + hh * 4;
            g_pb[(size_t)h * (NN * NN) + pidx] = inv * (S[h] - mu * cons[8 + h]) + cons[h];
        }
        return;
    }

    // ---------- dots: NT GEMM, 64x64 warp tiles, split-K 4 ----------
    const int h = blockIdx.z & 7, part = blockIdx.z >> 3;
    const int i0 = blockIdx.y * 128, j0 = blockIdx.x * 128;
    float* Asb = smem;
    float* Bsb = smem + PIPE * 128 * 20;
    const int wm = (warp >> 1) * 64, wn = (warp & 1) * 64;
    const int g = lane >> 2, c = lane & 3;
    const int lr = t >> 2;
    const int lq = (t & 3) * 4;
    const int nit = 1024 / 16;   // 64

    auto stage = [&](int it) {
        if (it < nit) {
            const int kg = part * 1024 + it * 16;
            const int r = kg >> 6, d0 = (kg & 63) + lq;
            const float* Abase = g_q + ((size_t)r * NN + i0) * 512 + h * 64 + d0;
            const float* Bbase = g_k + ((size_t)r * NN + j0) * 512 + h * 64 + d0;
            const int s = it % PIPE;
#pragma unroll
            for (int rr = 0; rr < 128; rr += 32) {
                cp16(&Asb[((size_t)s * 128 + lr + rr) * 20 + lq],
                     Abase + (size_t)(lr + rr) * 512);
                cp16(&Bsb[((size_t)s * 128 + lr + rr) * 20 + lq],
                     Bbase + (size_t)(lr + rr) * 512);
            }
        }
        cp_commit();
    };

    float acc[4][8][4] = {};
    stage(0); stage(1);
    for (int it = 0; it < nit; ++it) {
        const int s = it % PIPE;
        cp_wait<1>();
        __syncthreads();
#pragma unroll
        for (int ks = 0; ks < 16; ks += 8) {
            unsigned af[4][4], bf[8][2];
#pragma unroll
            for (int mf = 0; mf < 4; mf++) {
                int r0 = wm + mf * 16;
                af[mf][0] = __float_as_uint(Asb[((size_t)s * 128 + r0 + g) * 20 + ks + c]);
                af[mf][1] = __float_as_uint(Asb[((size_t)s * 128 + r0 + g + 8) * 20 + ks + c]);
                af[mf][2] = __float_as_uint(Asb[((size_t)s * 128 + r0 + g) * 20 + ks + c + 4]);
                af[mf][3] = __float_as_uint(Asb[((size_t)s * 128 + r0 + g + 8) * 20 + ks + c + 4]);
            }
#pragma unroll
            for (int nf = 0; nf < 8; nf++) {
                int n = wn + nf * 8 + g;
                bf[nf][0] = __float_as_uint(Bsb[((size_t)s * 128 + n) * 20 + ks + c]);
                bf[nf][1] = __float_as_uint(Bsb[((size_t)s * 128 + n) * 20 + ks + c + 4]);
            }
#pragma unroll
            for (int mf = 0; mf < 4; mf++)
#pragma unroll
                for (int nf = 0; nf < 8; nf++) mma8(acc[mf][nf], af[mf], bf[nf]);
        }
        stage(it + 2);
    }

    float* Cb = (part == 0 ? g_dots : part == 1 ? g_dots1 : part == 2 ? g_dots2 : g_dots3)
                + (size_t)h * (NN * NN);
#pragma unroll
    for (int mf = 0; mf < 4; mf++) {
        const int row = i0 + wm + mf * 16 + g;
#pragma unroll
        for (int nf = 0; nf < 8; nf++) {
            const int col = j0 + wn + nf * 8 + 2 * c;
            *(float2*)(Cb + (size_t)row * NN + col) =
                make_float2(acc[mf][nf][0], acc[mf][nf][1]);
            *(float2*)(Cb + (size_t)(row + 8) * NN + col) =
                make_float2(acc[mf][nf][2], acc[mf][nf][3]);
        }
    }
}

// ---------------- launch 6: softmax, 256 thr/row -------------------------------
__global__ void __launch_bounds__(256)
softmax_kernel()
{
    const int i = blockIdx.x, h = blockIdx.y;
    const size_t off = ((size_t)h * NN + i) * NN;
    float* row = g_dots + off;
    const float* r1 = g_dots1 + off;
    const float* r2 = g_dots2 + off;
    const float* r3 = g_dots3 + off;
    const float* pbr = g_pb + off;
    const int t = threadIdx.x;  // 256
    __shared__ float red[256];
    float v[2];
    float mx = -1e30f;
#pragma unroll
    for (int e = 0; e < 2; e++) {
        const int j = t * 2 + e;
        v[e] = row[j] + r1[j] + r2[j] + r3[j] + pbr[j];
        mx = fmaxf(mx, v[e]);
    }
    red[t] = mx; __syncthreads();
#pragma unroll
    for (int s = 128; s; s >>= 1) { if (t < s) red[t] = fmaxf(red[t], red[t + s]); __syncthreads(); }
    const float M = red[0];
    __syncthreads();
    float sum = 0.f;
#pragma unroll
    for (int e = 0; e < 2; e++) { v[e] = expf(v[e] - M); sum += v[e]; }
    red[t] = sum; __syncthreads();
#pragma unroll
    for (int s = 128; s; s >>= 1) { if (t < s) red[t] += red[t + s]; __syncthreads(); }
    const float inv = 1.f / red[0];
    *(float2*)(row + t * 2) = make_float2(f2tff(v[0] * inv), f2tff(v[1] * inv));
}

// ---------------- launch 7: ctx NN GEMM, 64x64 warp tiles, 128 thr -------------
__global__ void __launch_bounds__(128)
ctx_nn()
{
    const int h  = blockIdx.z;
    const int i0 = blockIdx.y * 128, n0 = blockIdx.x * 128;
    extern __shared__ float smem[];
    float* Asb = smem;
    float* Bsb = smem + PIPE * 128 * 20;
    const int t = threadIdx.x, lane = t & 31, warp = t >> 5;
    const int wm = (warp >> 1) * 64, wn = (warp & 1) * 64;
    const int g = lane >> 2, c = lane & 3;
    const int lr = t >> 2, lq = (t & 3) * 4;
    const int bcol = (t & 31) * 4;
    const int brow = t >> 5;

    const float* Ab = g_dots + (size_t)h * (NN * NN) + (size_t)i0 * NN;
    const int cgB = n0 + bcol;
    const float* Bptr = g_v + ((size_t)(cgB >> 6) * NN) * 512 + h * 64 + (cgB & 63);
    const int nit = NN / 16;   // 32

    auto stage = [&](int it) {
        if (it < nit) {
            const int k0 = it * 16, s = it % PIPE;
#pragma unroll
            for (int rr = 0; rr < 128; rr += 32)
                cp16(&Asb[((size_t)s * 128 + lr + rr) * 20 + lq],
                     Ab + (size_t)(lr + rr) * NN + k0 + lq);
#pragma unroll
            for (int j = 0; j < 4; j++) {
                const int kr = brow + j * 4;
                cp16(&Bsb[((size_t)s * 16 + kr) * 136 + bcol],
                     Bptr + (size_t)(k0 + kr) * 512);
            }
        }
        cp_commit();
    };

    float acc[4][8][4] = {};
    stage(0); stage(1);
    for (int it = 0; it < nit; ++it) {
        const int s = it % PIPE;
        cp_wait<1>();
        __syncthreads();
#pragma unroll
        for (int ks = 0; ks < 16; ks += 8) {
            unsigned af[4][4], bf[8][2];
#pragma unroll
            for (int mf = 0; mf < 4; mf++) {
                int r0 = wm + mf * 16;
                af[mf][0] = __float_as_uint(Asb[((size_t)s * 128 + r0 + g) * 20 + ks + c]);
                af[mf][1] = __float_as_uint(Asb[((size_t)s * 128 + r0 + g + 8) * 20 + ks + c]);
                af[mf][2] = __float_as_uint(Asb[((size_t)s * 128 + r0 + g) * 20 + ks + c + 4]);
                af[mf][3] = __float_as_uint(Asb[((size_t)s * 128 + r0 + g + 8) * 20 + ks + c + 4]);
            }
#pragma unroll
            for (int nf = 0; nf < 8; nf++) {
                int n = wn + nf * 8 + g;
                bf[nf][0] = __float_as_uint(Bsb[((size_t)s * 16 + ks + c) * 136 + n]);
                bf[nf][1] = __float_as_uint(Bsb[((size_t)s * 16 + ks + c + 4) * 136 + n]);
            }
#pragma unroll
            for (int mf = 0; mf < 4; mf++)
#pragma unroll
                for (int nf = 0; nf < 8; nf++) mma8(acc[mf][nf], af[mf], bf[nf]);
        }
        stage(it + 2);
    }

#pragma unroll
    for (int mf = 0; mf < 4; mf++) {
        const int row = i0 + wm + mf * 16 + g;
#pragma unroll
        for (int nf = 0; nf < 8; nf++) {
            const int col = n0 + wn + nf * 8 + 2 * c;
            const int rg = col >> 6, dd = col & 63;
            float* p0 = g_ctx + ((size_t)rg * NN + row) * INNERR + h * 64 + dd;
            float* p1 = g_ctx + ((size_t)rg * NN + row + 8) * INNERR + h * 64 + dd;
            *(float2*)p0 = make_float2(acc[mf][nf][0], acc[mf][nf][1]);
            *(float2*)p1 = make_float2(acc[mf][nf][2], acc[mf][nf][3]);
        }
    }
}

// ---------------- launch 8: output projection, 64x64 warp tiles, 128 thr -------
__global__ void __launch_bounds__(128)
out_gemm(const float* __restrict__ bias, float* __restrict__ C)
{
    extern __shared__ float smem[];
    float* Asb = smem;
    float* Bsb = smem + PIPE * 128 * 20;
    const int t = threadIdx.x, lane = t & 31, warp = t >> 5;
    const int i0 = blockIdx.y * 128;
    const int wm = (warp >> 1) * 64, wn = (warp & 1) * 64;
    const int g = lane >> 2, c = lane & 3;
    const int lr = t >> 2, lq = (t & 3) * 4;
    const int bcol = (t & 31) * 4;
    const int brow = t >> 5;

    const float* Ab = g_ctx + (size_t)i0 * INNERR;
    const int nit = INNERR / 16;   // 32

    auto stage = [&](int it) {
        if (it < nit) {
            const int k0 = it * 16, s = it % PIPE;
#pragma unroll
            for (int rr = 0; rr < 128; rr += 32)
                cp16(&Asb[((size_t)s * 128 + lr + rr) * 20 + lq],
                     Ab + (size_t)(lr + rr) * INNERR + k0 + lq);
#pragma unroll
            for (int j = 0; j < 4; j++) {
                const int kr = brow + j * 4;
                cp16(&Bsb[((size_t)s * 16 + kr) * 136 + bcol],
                     g_wo + (size_t)(k0 + kr) * DIMM + bcol);
            }
        }
        cp_commit();
    };

    float acc[4][8][4] = {};
    stage(0); stage(1);
    for (int it = 0; it < nit; ++it) {
        const int s = it % PIPE;
        cp_wait<1>();
        __syncthreads();
#pragma unroll
        for (int ks = 0; ks < 16; ks += 8) {
            unsigned af[4][4], bf[8][2];
#pragma unroll
            for (int mf = 0; mf < 4; mf++) {
                int r0 = wm + mf * 16;
                af[mf][0] = __float_as_uint(Asb[((size_t)s * 128 + r0 + g) * 20 + ks + c]);
                af[mf][1] = __float_as_uint(Asb[((size_t)s * 128 + r0 + g + 8) * 20 + ks + c]);
                af[mf][2] = __float_as_uint(Asb[((size_t)s * 128 + r0 + g) * 20 + ks + c + 4]);
                af[mf][3] = __float_as_uint(Asb[((size_t)s * 128 + r0 + g + 8) * 20 + ks + c + 4]);
            }
#pragma unroll
            for (int nf = 0; nf < 8; nf++) {
                int n = wn + nf * 8 + g;
                bf[nf][0] = __float_as_uint(Bsb[((size_t)s * 16 + ks + c) * 136 + n]);
                bf[nf][1] = __float_as_uint(Bsb[((size_t)s * 16 + ks + c + 4) * 136 + n]);
            }
#pragma unroll
            for (int mf = 0; mf < 4; mf++)
#pragma unroll
                for (int nf = 0; nf < 8; nf++) mma8(acc[mf][nf], af[mf], bf[nf]);
        }
        stage(it + 2);
    }

#pragma unroll
    for (int mf = 0; mf < 4; mf++) {
        const int row0 = i0 + wm + mf * 16 + g;
#pragma unroll
        for (int nf = 0; nf < 8; nf++) {
            const int col = wn + nf * 8 + 2 * c;
            float b0 = bias[col], b1 = bias[col + 1];
            *(float2*)(C + (size_t)row0 * DIMM + col) =
                make_float2(acc[mf][nf][0] + b0, acc[mf][nf][1] + b1);
            *(float2*)(C + (size_t)(row0 + 8) * DIMM + col) =
                make_float2(acc[mf][nf][2] + b0, acc[mf][nf][3] + b1);
        }
    }
}

// ------------------------------ host ------------------------------------------
extern "C" void kernel_launch(void* const* d_in, const int* in_sizes, int n_in,
                              void* d_out, int out_size)
{
    const float* x     = (const float*)d_in[0];
    const float* pair  = (const float*)d_in[1];
    const float* Wq    = (const float*)d_in[2];
    const float* Wkv   = (const float*)d_in[3];
    const float* Wo    = (const float*)d_in[4];
    const float* bo    = (const float*)d_in[5];
    const float* lng   = (const float*)d_in[6];
    const float* lnb   = (const float*)d_in[7];
    const float* Wpair = (const float*)d_in[8];
    const float* Wsq   = (const float*)d_in[9];
    const float* bsq   = (const float*)d_in[10];
    const float* Wsk   = (const float*)d_in[11];
    const float* bsk   = (const float*)d_in[12];
    float* out = (float*)d_out;

    const int SM_GEMM = PIPE * (128 * 20 + 16 * 136) * 4;  // 56832
    const int SM_DOTS = PIPE * (128 * 20) * 2 * 4;         // 61440
    cudaFuncSetAttribute(skq_gemm, cudaFuncAttributeMaxDynamicSharedMemorySize, SM_GEMM);
    cudaFuncSetAttribute(qkv_gemm, cudaFuncAttributeMaxDynamicSharedMemorySize, SM_GEMM);
    cudaFuncSetAttribute(dots_pb,  cudaFuncAttributeMaxDynamicSharedMemorySize, SM_DOTS);
    cudaFuncSetAttribute(ctx_nn,   cudaFuncAttributeMaxDynamicSharedMemorySize, SM_GEMM);
    cudaFuncSetAttribute(out_gemm, cudaFuncAttributeMaxDynamicSharedMemorySize, SM_GEMM);

    const int TOT4 = (RR * NN * DIMM + DIMM * INNERR + DIMM * 2 * INNERR
                      + INNERR * DIMM + 2 * DIMM * DIMM) / 4;

    // 1: tf32 rounding
    round_all<<<(TOT4 + 255) / 256, 256>>>(x, Wq, Wkv, Wo, Wsk, Wsq);
    // 2: merged sk + sq projections
    skq_gemm<<<dim3(1, 260), 256, SM_GEMM>>>(bsk, bsq);
    // 3: row weights (coalesced)
    rowweight_kernel<<<NN, 256>>>();
    // 4: q + kv projections  (MEASURED SLOT, R13 config)
    qkv_gemm<<<dim3(12, (RR * NN) / 128), 256, SM_GEMM>>>();
    // 5: merged dots (split-K 4) + pair bias
    dots_pb<<<dim3(4, 4, 32 + 512), 128, SM_DOTS>>>(pair, lng, lnb, Wpair);
    // 6: softmax (sum 4 parts + pair bias)
    softmax_kernel<<<dim3(NN, HH), 256>>>();
    // 7: attn @ V
    ctx_nn<<<dim3(32, 4, HH), 128, SM_GEMM>>>();
    // 8: output projection
    out_gemm<<<dim3(1, (RR * NN) / 128), 128, SM_GEMM>>>(bo, out);
}